// round 1
// baseline (speedup 1.0000x reference)
#include <cuda_runtime.h>
#include <cuda_bf16.h>

// ---------------------------------------------------------------------------
// Encoder_59425167507712: 4-layer transformer encoder, fp32.
// B=8, S=512, D=1024, DK=64 (head-0 only per source bug), FF=4096, L=4.
// Strategy (round 0): fp32 SMEM-tiled GEMM (128x128x8, 8x8 micro) with fused
// epilogues (bias / bias+relu / residual+BN), batched GEMMs for attention.
// ---------------------------------------------------------------------------

#define Bq   8
#define Sq   512
#define Dm   1024
#define DKh  64
#define FFd  4096
#define NL   4
#define Mrows (Bq*Sq)   // 4096

// Scratch (device globals: no allocation allowed)
__device__ float g_x [(long)Mrows*Dm];     // 16 MB activations
__device__ float g_q [(long)Mrows*DKh];
__device__ float g_k [(long)Mrows*DKh];
__device__ float g_v [(long)Mrows*DKh];
__device__ float g_hd[(long)Mrows*DKh];
__device__ float g_sc[(long)Bq*Sq*Sq];     // 8 MB scores
__device__ float g_h [(long)Mrows*FFd];    // 64 MB FFN hidden

constexpr int BM = 128, BN = 128, BKt = 8, TM = 8, TN = 8;

enum { EPI_NONE = 0, EPI_BIAS = 1, EPI_BIAS_RELU = 2, EPI_RESID_BN = 3 };

// C[z] = epilogue( alpha * A[z] @ (TRANSB ? B[z]^T : B[z]) )
// A: [M,K] row-major. B: TRANSB ? [N,K] : [K,N] row-major.
// Requires M % 128 == 0, K % 8 == 0, N % 4 == 0 (all true for this model).
template <int EPI, bool TRANSB>
__global__ void __launch_bounds__(256, 2)
gemm_k(const float* __restrict__ A, const float* __restrict__ B,
       const float* __restrict__ bias, float* __restrict__ C,
       int M, int N, int K,
       long sA, long sB, long sC, float alpha,
       const float* __restrict__ resid,
       const float* __restrict__ gamma, const float* __restrict__ beta,
       const float* __restrict__ mean,  const float* __restrict__ var)
{
    __shared__ float As[BKt][BM + 4];
    __shared__ float Bs[BKt][BN + 4];

    A += (long)blockIdx.z * sA;
    B += (long)blockIdx.z * sB;
    C += (long)blockIdx.z * sC;

    const int m0 = blockIdx.y * BM;
    const int n0 = blockIdx.x * BN;
    const int tid = threadIdx.x;
    const int tx = tid & 15;        // 16 columns of threads
    const int ty = tid >> 4;        // 16 rows of threads

    // A tile load: 128 rows x 8 cols, float4 along K
    const int arow = tid >> 1;
    const int acol = (tid & 1) << 2;
    // B tile load (no trans): 8 rows x 128 cols, float4 along N
    const int brow = tid >> 5;
    const int bcol = (tid & 31) << 2;
    // B tile load (trans): row n = tid/2, float4 along K
    const int bn  = tid >> 1;
    const int bkk = (tid & 1) << 2;

    float acc[TM][TN];
#pragma unroll
    for (int i = 0; i < TM; i++)
#pragma unroll
        for (int j = 0; j < TN; j++) acc[i][j] = 0.f;

    for (int k0 = 0; k0 < K; k0 += BKt) {
        float4 av = *reinterpret_cast<const float4*>(
            A + (long)(m0 + arow) * K + k0 + acol);
        As[acol + 0][arow] = av.x;
        As[acol + 1][arow] = av.y;
        As[acol + 2][arow] = av.z;
        As[acol + 3][arow] = av.w;

        if (!TRANSB) {
            float4 bv = make_float4(0.f, 0.f, 0.f, 0.f);
            if (n0 + bcol < N)
                bv = *reinterpret_cast<const float4*>(
                    B + (long)(k0 + brow) * N + n0 + bcol);
            Bs[brow][bcol + 0] = bv.x;
            Bs[brow][bcol + 1] = bv.y;
            Bs[brow][bcol + 2] = bv.z;
            Bs[brow][bcol + 3] = bv.w;
        } else {
            float4 bv = make_float4(0.f, 0.f, 0.f, 0.f);
            if (n0 + bn < N)
                bv = *reinterpret_cast<const float4*>(
                    B + (long)(n0 + bn) * K + k0 + bkk);
            Bs[bkk + 0][bn] = bv.x;
            Bs[bkk + 1][bn] = bv.y;
            Bs[bkk + 2][bn] = bv.z;
            Bs[bkk + 3][bn] = bv.w;
        }
        __syncthreads();

#pragma unroll
        for (int kk = 0; kk < BKt; kk++) {
            float4 a0 = *reinterpret_cast<const float4*>(&As[kk][ty * TM]);
            float4 a1 = *reinterpret_cast<const float4*>(&As[kk][ty * TM + 4]);
            float4 b0 = *reinterpret_cast<const float4*>(&Bs[kk][tx * TN]);
            float4 b1 = *reinterpret_cast<const float4*>(&Bs[kk][tx * TN + 4]);
            float a[TM] = {a0.x, a0.y, a0.z, a0.w, a1.x, a1.y, a1.z, a1.w};
            float b[TN] = {b0.x, b0.y, b0.z, b0.w, b1.x, b1.y, b1.z, b1.w};
#pragma unroll
            for (int i = 0; i < TM; i++)
#pragma unroll
                for (int j = 0; j < TN; j++)
                    acc[i][j] = fmaf(a[i], b[j], acc[i][j]);
        }
        __syncthreads();
    }

#pragma unroll
    for (int i = 0; i < TM; i++) {
        const int m = m0 + ty * TM + i;
#pragma unroll
        for (int j = 0; j < TN; j++) {
            const int n = n0 + tx * TN + j;
            if (n < N) {
                float v = acc[i][j] * alpha;
                if (EPI == EPI_BIAS || EPI == EPI_BIAS_RELU || EPI == EPI_RESID_BN)
                    v += bias[n];
                if (EPI == EPI_BIAS_RELU)
                    v = fmaxf(v, 0.f);
                if (EPI == EPI_RESID_BN) {
                    v += resid[(long)m * N + n];
                    v = gamma[n] * (v - mean[n]) * rsqrtf(var[n] + 1e-3f) + beta[n];
                }
                C[(long)m * N + n] = v;
            }
        }
    }
}

// x[b*S+s, d] = emb[seq[b*S+s], d] + pes[s, 0]
__global__ void embed_k(const int* __restrict__ seq,
                        const float* __restrict__ emb,
                        const float* __restrict__ pes,
                        float* __restrict__ x)
{
    long idx = (long)blockIdx.x * blockDim.x + threadIdx.x;
    int d = (int)(idx & (Dm - 1));
    long bs = idx >> 10;
    int s = (int)(bs & (Sq - 1));
    x[idx] = emb[(long)seq[bs] * Dm + d] + pes[(long)s * Dm];
}

// Row softmax over 512 columns; one block (256 threads) per row.
__global__ void softmax_k(float* __restrict__ S)
{
    float* p = S + (long)blockIdx.x * Sq;
    const int t = threadIdx.x;
    __shared__ float red[256];

    float v0 = p[t], v1 = p[t + 256];
    red[t] = fmaxf(v0, v1);
    __syncthreads();
    for (int o = 128; o > 0; o >>= 1) {
        if (t < o) red[t] = fmaxf(red[t], red[t + o]);
        __syncthreads();
    }
    const float m = red[0];
    __syncthreads();

    float e0 = __expf(v0 - m), e1 = __expf(v1 - m);
    red[t] = e0 + e1;
    __syncthreads();
    for (int o = 128; o > 0; o >>= 1) {
        if (t < o) red[t] += red[t + o];
        __syncthreads();
    }
    const float inv = 1.f / red[0];
    p[t]       = e0 * inv;
    p[t + 256] = e1 * inv;
}

template <int EPI, bool TB>
static inline void gemm(const float* A, const float* B, const float* bias,
                        float* C, int M, int N, int K, int batch,
                        long sA, long sB, long sC, float alpha,
                        const float* resid = nullptr,
                        const float* gamma = nullptr, const float* beta = nullptr,
                        const float* mean = nullptr,  const float* var = nullptr)
{
    dim3 grid((N + BN - 1) / BN, M / BM, batch);
    gemm_k<EPI, TB><<<grid, 256>>>(A, B, bias, C, M, N, K, sA, sB, sC, alpha,
                                   resid, gamma, beta, mean, var);
}

extern "C" void kernel_launch(void* const* d_in, const int* in_sizes, int n_in,
                              void* d_out, int out_size)
{
    const int*   seq = (const int*)  d_in[0];
    const float* emb = (const float*)d_in[1];
    const float* pes = (const float*)d_in[2];
    const float* wq  = (const float*)d_in[3];
    const float* bq  = (const float*)d_in[4];
    const float* wk  = (const float*)d_in[5];
    const float* bk  = (const float*)d_in[6];
    const float* wv  = (const float*)d_in[7];
    const float* bv  = (const float*)d_in[8];
    const float* wo  = (const float*)d_in[9];
    const float* bo  = (const float*)d_in[10];
    const float* ag  = (const float*)d_in[11];
    const float* ab  = (const float*)d_in[12];
    const float* am  = (const float*)d_in[13];
    const float* avv = (const float*)d_in[14];
    const float* w1  = (const float*)d_in[15];
    const float* b1  = (const float*)d_in[16];
    const float* w2  = (const float*)d_in[17];
    const float* b2  = (const float*)d_in[18];
    const float* fg  = (const float*)d_in[19];
    const float* fb  = (const float*)d_in[20];
    const float* fm  = (const float*)d_in[21];
    const float* fv  = (const float*)d_in[22];
    float* out = (float*)d_out;

    float *px, *pq, *pk, *pv, *phd, *psc, *ph;
    cudaGetSymbolAddress((void**)&px,  g_x);
    cudaGetSymbolAddress((void**)&pq,  g_q);
    cudaGetSymbolAddress((void**)&pk,  g_k);
    cudaGetSymbolAddress((void**)&pv,  g_v);
    cudaGetSymbolAddress((void**)&phd, g_hd);
    cudaGetSymbolAddress((void**)&psc, g_sc);
    cudaGetSymbolAddress((void**)&ph,  g_h);

    embed_k<<<(Mrows * Dm) / 256, 256>>>(seq, emb, pes, px);

    for (int l = 0; l < NL; l++) {
        // Q, K, V projections: [4096,1024]@[1024,64] + bias
        gemm<EPI_BIAS, false>(px, wq + (long)l * Dm * DKh, bq + l * DKh, pq,
                              Mrows, DKh, Dm, 1, 0, 0, 0, 1.f);
        gemm<EPI_BIAS, false>(px, wk + (long)l * Dm * DKh, bk + l * DKh, pk,
                              Mrows, DKh, Dm, 1, 0, 0, 0, 1.f);
        gemm<EPI_BIAS, false>(px, wv + (long)l * Dm * DKh, bv + l * DKh, pv,
                              Mrows, DKh, Dm, 1, 0, 0, 0, 1.f);

        // scores = Q @ K^T * 1/sqrt(64), batched over B
        gemm<EPI_NONE, true>(pq, pk, nullptr, psc, Sq, Sq, DKh, Bq,
                             (long)Sq * DKh, (long)Sq * DKh, (long)Sq * Sq,
                             0.125f);

        softmax_k<<<Mrows, 256>>>(psc);

        // head = P @ V, batched over B
        gemm<EPI_NONE, false>(psc, pv, nullptr, phd, Sq, DKh, Sq, Bq,
                              (long)Sq * Sq, (long)Sq * DKh, (long)Sq * DKh,
                              1.f);

        // x = BN(x + head @ wo + bo)
        gemm<EPI_RESID_BN, false>(phd, wo + (long)l * DKh * Dm, bo + l * Dm, px,
                                  Mrows, Dm, DKh, 1, 0, 0, 0, 1.f,
                                  px, ag + l * Dm, ab + l * Dm,
                                  am + l * Dm, avv + l * Dm);

        // h = relu(x @ w1 + b1)
        gemm<EPI_BIAS_RELU, false>(px, w1 + (long)l * Dm * FFd, b1 + l * FFd,
                                   ph, Mrows, FFd, Dm, 1, 0, 0, 0, 1.f);

        // x = BN(x + h @ w2 + b2); final layer writes straight to d_out
        float* dst = (l == NL - 1) ? out : px;
        gemm<EPI_RESID_BN, false>(ph, w2 + (long)l * FFd * Dm, b2 + l * Dm, dst,
                                  Mrows, Dm, FFd, 1, 0, 0, 0, 1.f,
                                  px, fg + l * Dm, fb + l * Dm,
                                  fm + l * Dm, fv + l * Dm);
    }
}